// round 17
// baseline (speedup 1.0000x reference)
#include <cuda_runtime.h>
#include <cuda_bf16.h>

#define BSZ 32
#define TT  200
#define RR  512
#define FF  128
#define BR  4
#define CC  10
#define K2  1024
#define NROWS 2048
#define VTH 0.5f

#define NCTA_TOTAL 148
#define GEMM_CTAS  128
#define NTH 1024

#define KT_STRIDE 36      // floats per spike-kT row
#define ROWSTRIDE 272     // cur section + spk section, each padded to 8
#define OUT0 (BSZ*CC*TT)
#define SLOT (RR*BSZ)     // 16384 floats
#define AHEAD 8           // cur-proj lookahead
#define RINGP 9           // pA ring depth (> AHEAD)
#define LOOK 16           // currents production lookahead

// -------- device scratch --------
__device__ float          g_currents[TT * SLOT];       // [T][R][B]
__device__ float          g_ring[4][SLOT];             // epoch-encoded spikes
__device__ unsigned short g_pidx16[NROWS * ROWSTRIDE]; // cur: k ; spk: (k-512)*36
__device__ float          g_wv [NROWS * ROWSTRIDE];
__device__ unsigned       g_secs[NROWS];               // ncurP | nspkP<<16
__device__ unsigned       g_ccnt[TT * 8];              // currents-ready shard counters
__device__ volatile unsigned g_ro[32];                 // readout staged-step+1

__device__ __forceinline__ float sigmoidf_(float x) { return 1.f / (1.f + __expf(-x)); }

__device__ __forceinline__ float4 ldcg4(const float4* p) {
    float4 v;
    asm volatile("ld.global.cg.v4.f32 {%0,%1,%2,%3}, [%4];"
                 : "=f"(v.x), "=f"(v.y), "=f"(v.z), "=f"(v.w) : "l"(p));
    return v;
}

__global__ void k_init() {
    int tid = blockIdx.x * blockDim.x + threadIdx.x;
    for (int i = tid; i < 4 * SLOT; i += gridDim.x * blockDim.x)
        ((float*)g_ring)[i] = (i >= 3 * SLOT) ? 1.0f : 0.0f;  // slot3: S(-1)=0,epoch1
    for (int i = tid; i < TT * 8; i += gridDim.x * blockDim.x) g_ccnt[i] = 0;
    if (tid < 32) g_ro[tid] = 0;
}

// compact rows: cur section (k<512, idx=k) then spk section (k>=512, idx=(k-512)*36)
__global__ void k_prep(const float* __restrict__ w_rnn,
                       const float* __restrict__ mask) {
    int row = blockIdx.x * 8 + (threadIdx.x >> 5);
    int lane = threadIdx.x & 31;
    if (row >= NROWS) return;
    unsigned short* pp = g_pidx16 + row * ROWSTRIDE;
    float*          wp = g_wv    + row * ROWSTRIDE;

    int base = 0;
    for (int c0 = 0; c0 < 512; c0 += 32) {
        float m = mask[(long long)row * K2 + c0 + lane];
        unsigned bal = __ballot_sync(0xffffffffu, m != 0.f);
        int pre = __popc(bal & ((1u << lane) - 1u));
        if (m != 0.f) {
            pp[base + pre] = (unsigned short)(c0 + lane);
            wp[base + pre] = w_rnn[(long long)row * K2 + c0 + lane];
        }
        base += __popc(bal);
    }
    int ncur = base, ncurP = (ncur + 7) & ~7;
    if (lane < ncurP - ncur) { pp[ncur + lane] = 0; wp[ncur + lane] = 0.f; }

    base = 0;
    for (int c0 = 512; c0 < K2; c0 += 32) {
        float m = mask[(long long)row * K2 + c0 + lane];
        unsigned bal = __ballot_sync(0xffffffffu, m != 0.f);
        int pre = __popc(bal & ((1u << lane) - 1u));
        if (m != 0.f) {
            pp[ncurP + base + pre] = (unsigned short)((c0 + lane - 512) * KT_STRIDE);
            wp[ncurP + base + pre] = w_rnn[(long long)row * K2 + c0 + lane];
        }
        base += __popc(bal);
    }
    int nspk = base, nspkP = (nspk + 7) & ~7;
    if (lane < nspkP - nspk) { pp[ncurP + nspk + lane] = 0; wp[ncurP + nspk + lane] = 0.f; }
    if (lane == 0) g_secs[row] = (unsigned)ncurP | ((unsigned)nspkP << 16);
}

// paired sparse GEMM (smem kT, spikes). Parity-permuted blocks {e0..e3,o0..o3}.
__device__ __forceinline__ void gemm_pair(
    const float* wp, const unsigned short* ip, int cnt,
    const char* ktp, int off4, float* dst, int lane)
{
    float a0 = 0.f, a1 = 0.f, b0 = 0.f, b1 = 0.f;
    for (int j = 0; j < cnt; j += 8) {
        float4 w = *(const float4*)(wp + j + off4);
        uint2  q = *(const uint2*)(ip + j + off4);
        unsigned o0 = (q.x & 0xFFFFu) * 4u;
        unsigned o1 = (q.x >> 16) * 4u;
        unsigned o2 = (q.y & 0xFFFFu) * 4u;
        unsigned o3 = (q.y >> 16) * 4u;
        float2 v0 = *(const float2*)(ktp + o0);
        float2 v1 = *(const float2*)(ktp + o1);
        float2 v2 = *(const float2*)(ktp + o2);
        float2 v3 = *(const float2*)(ktp + o3);
        a0 = fmaf(w.x, v0.x, a0); a1 = fmaf(w.x, v0.y, a1);
        b0 = fmaf(w.y, v1.x, b0); b1 = fmaf(w.y, v1.y, b1);
        a0 = fmaf(w.z, v2.x, a0); a1 = fmaf(w.z, v2.y, a1);
        b0 = fmaf(w.w, v3.x, b0); b1 = fmaf(w.w, v3.y, b1);
    }
    a0 += b0; a1 += b1;
    a0 += __shfl_xor_sync(0xffffffffu, a0, 16);
    a1 += __shfl_xor_sync(0xffffffffu, a1, 16);
    if (lane < 16) *(float2*)(dst + lane * 2) = make_float2(a0, a1);
}

// paired sparse GEMM gathering currents straight from GMEM via L1.
__device__ __forceinline__ void gemm_pair_g(
    const float* wp, const unsigned short* ip, int cnt,
    const char* cb, int off4, float* dst, int lane)
{
    float a0 = 0.f, a1 = 0.f, b0 = 0.f, b1 = 0.f;
    for (int j = 0; j < cnt; j += 8) {
        float4 w = *(const float4*)(wp + j + off4);
        uint2  q = *(const uint2*)(ip + j + off4);
        float2 v0 = __ldg((const float2*)(cb + ((q.x & 0xFFFFu) << 7)));
        float2 v1 = __ldg((const float2*)(cb + ((q.x >> 16) << 7)));
        float2 v2 = __ldg((const float2*)(cb + ((q.y & 0xFFFFu) << 7)));
        float2 v3 = __ldg((const float2*)(cb + ((q.y >> 16) << 7)));
        a0 = fmaf(w.x, v0.x, a0); a1 = fmaf(w.x, v0.y, a1);
        b0 = fmaf(w.y, v1.x, b0); b1 = fmaf(w.y, v1.y, b1);
        a0 = fmaf(w.z, v2.x, a0); a1 = fmaf(w.z, v2.y, a1);
        b0 = fmaf(w.w, v3.x, b0); b1 = fmaf(w.w, v3.y, b1);
    }
    a0 += b0; a1 += b1;
    a0 += __shfl_xor_sync(0xffffffffu, a0, 16);
    a1 += __shfl_xor_sync(0xffffffffu, a1, 16);
    if (lane < 16) *(float2*)(dst + lane * 2) = make_float2(a0, a1);
}

// poll currents-ready shard counters for step tp (targets: shards 0-3: 384, 4-7: 512)
__device__ __forceinline__ void poll_cur(int tp, int lane) {
    if (lane < 8) {
        unsigned tgt = (lane < 4) ? 384u : 512u;
        while (*(volatile unsigned*)&g_ccnt[tp * 8 + lane] < tgt) __nanosleep(40);
    }
    __syncwarp();
    asm volatile("" ::: "memory");
}

// smem float offsets (GEMM CTAs)
#define SW_OFF   0
#define SI_OFF   (SW_OFF + 16*ROWSTRIDE)
#define KT_OFF   (SI_OFF + 8*ROWSTRIDE)
#define PA_OFF   (KT_OFF + RR*KT_STRIDE)
#define PB_OFF   (PA_OFF + RINGP*1024)
#define SD_OFF   (PB_OFF + 1024)
#define SM_OFF   (SD_OFF + 16*33)
#define SS_OFF   (SM_OFF + 4*33)
#define HB_OFF   (SS_OFF + 4*33)
#define BT_OFF   (HB_OFF + 128*9)
#define BN_OFF   (BT_OFF + 16)
#define AL_OFF   (BN_OFF + 16)
#define SEC_OFF  (AL_OFF + 8)
#define SMEM_FLOATS (SEC_OFF + 24)

__global__ void __launch_bounds__(NTH, 1)
k_recurrent(const float* __restrict__ inp,
            const float* __restrict__ w_in,
            const float* __restrict__ b_in,
            const float* __restrict__ gating,
            const float* __restrict__ b_rnn,
            const float* __restrict__ tau_m,
            const float* __restrict__ tau_n,
            const float* __restrict__ w_ro,
            const float* __restrict__ b_ro,
            const float* __restrict__ tau_m_ro,
            float* __restrict__ out) {
    extern __shared__ float smf[];
    int tid = threadIdx.x, lane = tid & 31, wid = tid >> 5;
    int bid = blockIdx.x;

    if (bid >= GEMM_CTAS) {
        // ======== readout CTAs (20): epoch-poll ring, stage, dot ========
        float* s_wro = smf;
        float* s_sp  = s_wro + CC * RR;
        for (int i = tid; i < CC * RR; i += NTH) s_wro[i] = w_ro[i];
        __syncthreads();

        int task = (bid - GEMM_CTAS) * 32 + wid;
        bool act = task < BSZ * CC;
        int b_ = act ? task / CC : 0, c_ = act ? task % CC : 0;
        float ao = sigmoidf_(tau_m_ro[c_]), bro = b_ro[c_];
        float m0 = 0.f, sp0 = 0.f;
        int myidx = bid - GEMM_CTAS;

        for (int t = 0; t < TT; t++) {
            const float4* slot4 = (const float4*)(g_ring[t & 3]);
            float thr = (float)(t + 2);
            float4 v0, v1, v2, v3;
            for (;;) {
                v0 = ldcg4(slot4 + tid);
                v1 = ldcg4(slot4 + tid + 1024);
                v2 = ldcg4(slot4 + tid + 2048);
                v3 = ldcg4(slot4 + tid + 3072);
                bool ok = v0.x >= thr && v0.y >= thr && v0.z >= thr && v0.w >= thr
                       && v1.x >= thr && v1.y >= thr && v1.z >= thr && v1.w >= thr
                       && v2.x >= thr && v2.y >= thr && v2.z >= thr && v2.w >= thr
                       && v3.x >= thr && v3.y >= thr && v3.z >= thr && v3.w >= thr;
                if (ok) break;
                __nanosleep(40);
            }
            {
                int i0 = tid, r, b4;
                r = i0 >> 3; b4 = (i0 & 7) * 4;
                s_sp[r * 33 + b4] = v0.x - thr; s_sp[r * 33 + b4 + 1] = v0.y - thr;
                s_sp[r * 33 + b4 + 2] = v0.z - thr; s_sp[r * 33 + b4 + 3] = v0.w - thr;
                i0 = tid + 1024; r = i0 >> 3; b4 = (i0 & 7) * 4;
                s_sp[r * 33 + b4] = v1.x - thr; s_sp[r * 33 + b4 + 1] = v1.y - thr;
                s_sp[r * 33 + b4 + 2] = v1.z - thr; s_sp[r * 33 + b4 + 3] = v1.w - thr;
                i0 = tid + 2048; r = i0 >> 3; b4 = (i0 & 7) * 4;
                s_sp[r * 33 + b4] = v2.x - thr; s_sp[r * 33 + b4 + 1] = v2.y - thr;
                s_sp[r * 33 + b4 + 2] = v2.z - thr; s_sp[r * 33 + b4 + 3] = v2.w - thr;
                i0 = tid + 3072; r = i0 >> 3; b4 = (i0 & 7) * 4;
                s_sp[r * 33 + b4] = v3.x - thr; s_sp[r * 33 + b4 + 1] = v3.y - thr;
                s_sp[r * 33 + b4 + 2] = v3.z - thr; s_sp[r * 33 + b4 + 3] = v3.w - thr;
            }
            __syncthreads();
            if (tid == 0) g_ro[myidx] = (unsigned)(t + 1);
            if (act) {
                float sum = 0.f;
                #pragma unroll
                for (int i = 0; i < RR; i += 32)
                    sum += s_sp[(i + lane) * 33 + b_] * s_wro[c_ * RR + i + lane];
                #pragma unroll
                for (int o = 16; o; o >>= 1) sum += __shfl_xor_sync(0xffffffffu, sum, o);
                m0 = m0 * ao + (1.f - ao) * (sum + bro) - VTH * sp0;
                sp0 = (m0 - VTH) > 0.f ? 1.f : 0.f;
                if (lane == 0) out[(long long)task * TT + t] = m0;
            }
            __syncthreads();
        }
        return;
    }

    // ======== GEMM CTAs (128): 16 rows (4 neurons) x 32 batches ========
    float*          s_w    = smf + SW_OFF;
    unsigned short* s_idx  = (unsigned short*)(smf + SI_OFF);
    float*          s_kT   = smf + KT_OFF;
    float*          s_pA   = smf + PA_OFF;
    float*          s_pB   = smf + PB_OFF;
    float*          s_d    = smf + SD_OFF;
    float*          s_mem  = smf + SM_OFF;
    float*          s_spk  = smf + SS_OFF;
    float*          s_hist = smf + HB_OFF;
    float*          s_beta = smf + BT_OFF;
    float*          s_brnn = smf + BN_OFF;
    float*          s_alph = smf + AL_OFF;
    unsigned*       s_secs = (unsigned*)(smf + SEC_OFF);

    int row0 = bid * 16, n0 = bid * 4;

    for (int i = tid; i < 16 * ROWSTRIDE; i += NTH) {
        int p = i & 7, src = (i & ~7) + ((p < 4) ? 2 * p : 2 * p - 7);
        s_w[i]   = g_wv    [row0 * ROWSTRIDE + src];
        s_idx[i] = g_pidx16[row0 * ROWSTRIDE + src];
    }
    if (tid < 16) {
        s_secs[tid] = g_secs[row0 + tid];
        s_beta[tid] = sigmoidf_(tau_n[(n0 + (tid >> 2)) * BR + (tid & 3)]);
        s_brnn[tid] = b_rnn[row0 + tid];
    }
    if (tid < 4) s_alph[tid] = sigmoidf_(tau_m[n0 + tid]);
    for (int i = tid; i < 16 * 33; i += NTH) s_d[i] = 0.f;
    if (tid < 4 * 33) { s_mem[tid] = 0.f; s_spk[tid] = 0.f; }
    __syncthreads();

    const char* ktp  = (const char*)s_kT + (lane & 15) * 8;
    int off4 = (lane & 16) ? 4 : 0;
    int lboff = (lane & 15) * 8;

    float4 wi = __ldg(((const float4*)w_in) + lane);   // w_in[lane*4..lane*4+3]
    float bin0 = __ldg(b_in);

    int foff[4];
    #pragma unroll
    for (int j = 0; j < 4; j++) {
        int i = tid + j * 1024;
        foff[j] = (i >> 3) * KT_STRIDE + (i & 7) * 4;
    }

    // per-warp GEMM split
    int rowW = wid >> 1, halfW = wid & 1;
    unsigned secW = s_secs[rowW];
    int ncurPW = (int)(secW & 0xFFFF), nspkPW = (int)(secW >> 16);
    int hc = (ncurPW >> 4) << 3;
    int begC = halfW ? hc : 0;
    int cntC = halfW ? (ncurPW - hc) : hc;
    int hs = (nspkPW >> 4) << 3;
    int begS = ncurPW + (halfW ? hs : 0);
    int cntS = halfW ? (nspkPW - hs) : hs;
    const float*          wpC = s_w   + rowW * ROWSTRIDE + begC;
    const unsigned short* ipC = s_idx + rowW * ROWSTRIDE + begC;
    const float*          wpS = s_w   + rowW * ROWSTRIDE + begS;
    const unsigned short* ipS = s_idx + rowW * ROWSTRIDE + begS;
    int dstOff = halfW * 512 + rowW * 32;

    // ---- prologue 1: produce currents(0..LOOK-1) (warps 4..31, 5 dots each)
    if (wid >= 4) {
        for (int tp = 0; tp < LOOK; tp++) {
            #pragma unroll
            for (int j = 0; j < 5; j++) {
                int id = (wid - 4) + 28 * j;
                float s = 0.f;
                int rr_ = id >> 5, b = id & 31;
                if (id < 128) {
                    const float4* p = (const float4*)(inp
                        + (((long long)b * TT + tp) * RR + (n0 + rr_)) * FF) + lane;
                    float4 v = __ldg(p);
                    s = v.x * wi.x + v.y * wi.y + v.z * wi.z + v.w * wi.w;
                }
                #pragma unroll
                for (int o = 16; o; o >>= 1) s += __shfl_xor_sync(0xffffffffu, s, o);
                if (lane == 0 && id < 128)
                    g_currents[((long long)tp * RR + n0 + rr_) * BSZ + b] = s + bin0;
            }
            if (lane == 0) {
                __threadfence();
                atomicAdd(&g_ccnt[tp * 8 + (wid & 7)], 1u);
            }
        }
    }

    // ---- prologue 2: cur-proj for t = 0..AHEAD-1 into ring slots 0..7
    for (int j = 0; j < AHEAD; j++) {
        poll_cur(j, lane);
        const char* cb = (const char*)(g_currents + (long long)j * SLOT) + lboff;
        gemm_pair_g(wpC, ipC, cntC, cb, off4, s_pA + j * 1024 + dstOff, lane);
    }
    __syncthreads();

    int sR = 0, sW = AHEAD;

    for (int t = 0; t < TT; t++) {
        float gpre = 0.f;
        if (wid < 4)
            gpre = __ldg(&gating[((long long)lane * TT + t) * RR + n0 + wid]);

        // (B) poll-fill S(t-1) from ring slot (t-1)&3 (epoch >= t+1)
        {
            const float4* slot4 = (const float4*)(g_ring[(t + 3) & 3]);
            float thr = (float)(t + 1);
            float4 v0, v1, v2, v3;
            for (;;) {
                v0 = ldcg4(slot4 + tid);
                v1 = ldcg4(slot4 + tid + 1024);
                v2 = ldcg4(slot4 + tid + 2048);
                v3 = ldcg4(slot4 + tid + 3072);
                bool ok = v0.x >= thr && v0.y >= thr && v0.z >= thr && v0.w >= thr
                       && v1.x >= thr && v1.y >= thr && v1.z >= thr && v1.w >= thr
                       && v2.x >= thr && v2.y >= thr && v2.z >= thr && v2.w >= thr
                       && v3.x >= thr && v3.y >= thr && v3.z >= thr && v3.w >= thr;
                if (ok) break;
                __nanosleep(40);
            }
            v0.x -= thr; v0.y -= thr; v0.z -= thr; v0.w -= thr;
            v1.x -= thr; v1.y -= thr; v1.z -= thr; v1.w -= thr;
            v2.x -= thr; v2.y -= thr; v2.z -= thr; v2.w -= thr;
            v3.x -= thr; v3.y -= thr; v3.z -= thr; v3.w -= thr;
            *(float4*)(s_kT + foff[0]) = v0;
            *(float4*)(s_kT + foff[1]) = v1;
            *(float4*)(s_kT + foff[2]) = v2;
            *(float4*)(s_kT + foff[3]) = v3;
        }
        __syncthreads();

        // (C1) spike GEMM -> s_pB
        gemm_pair(wpS, ipS, cntS, ktp, off4, s_pB + dstOff, lane);
        __syncthreads();

        // (D) wid<4: phase3 + publish | wid>=4: produce currents(t+LOOK)
        if (wid < 4) {
            int nl = wid, b = lane;
            const float* pA = s_pA + sR * 1024;
            float g = gpre;
            float lin = 0.f;
            #pragma unroll
            for (int br = 0; br < BR; br++) {
                int row = nl * 4 + br;
                float proj = pA[row * 32 + b] + pA[512 + row * 32 + b]
                           + s_pB[row * 32 + b] + s_pB[512 + row * 32 + b]
                           + s_brnn[row];
                float beta = s_beta[row];
                float dold = s_d[row * 33 + b];
                float dnew = beta * dold + (1.f - beta) * proj;
                lin += dnew;
                s_d[row * 33 + b] = g * dnew + (1.f - g) * dold;
            }
            float alpha = s_alph[nl];
            float mold = s_mem[nl * 33 + b];
            float sold = s_spk[nl * 33 + b];
            float mnew = mold * alpha + (1.f - alpha) * lin - VTH * sold;
            float snew = (mnew - VTH) > 0.f ? 1.f : 0.f;
            float mg = g * mnew + (1.f - g) * mold;
            float sg = g * snew + (1.f - g) * sold;
            __stcg(&g_ring[t & 3][(n0 + nl) * BSZ + b], sg + (float)(t + 2));
            s_mem[nl * 33 + b] = mg;
            s_spk[nl * 33 + b] = sg;
            s_hist[(nl * 32 + b) * 9 + (t & 7)] = sg;
            if ((t & 7) == 7) {
                const float* h = s_hist + (nl * 32 + b) * 9;
                float4 w0 = make_float4(h[0], h[1], h[2], h[3]);
                float4 w1 = make_float4(h[4], h[5], h[6], h[7]);
                long long base = OUT0 + ((long long)b * RR + (n0 + nl)) * TT + (t - 7);
                *(float4*)(out + base) = w0;
                *(float4*)(out + base + 4) = w1;
            }
        } else {
            int tp = t + LOOK;
            if (tp < TT) {
                #pragma unroll
                for (int j = 0; j < 5; j++) {
                    int id = (wid - 4) + 28 * j;
                    float s = 0.f;
                    int rr_ = id >> 5, b = id & 31;
                    if (id < 128) {
                        const float4* p = (const float4*)(inp
                            + (((long long)b * TT + tp) * RR + (n0 + rr_)) * FF) + lane;
                        float4 v = __ldg(p);
                        s = v.x * wi.x + v.y * wi.y + v.z * wi.z + v.w * wi.w;
                    }
                    #pragma unroll
                    for (int o = 16; o; o >>= 1) s += __shfl_xor_sync(0xffffffffu, s, o);
                    if (lane == 0 && id < 128)
                        g_currents[((long long)tp * RR + n0 + rr_) * BSZ + b] = s + bin0;
                }
                if (lane == 0) {
                    __threadfence();
                    atomicAdd(&g_ccnt[tp * 8 + (wid & 7)], 1u);
                }
            }
            if (wid == 27 && t >= 2) {
                if (lane < 20) {
                    while (g_ro[lane] < (unsigned)(t - 2)) __nanosleep(40);
                }
                __syncwarp();
            }
        }

        // (C2) cur-proj for t+AHEAD into ring slot sW (slack work)
        if (t + AHEAD < TT) {
            poll_cur(t + AHEAD, lane);
            const char* cb = (const char*)(g_currents + (long long)(t + AHEAD) * SLOT)
                           + lboff;
            gemm_pair_g(wpC, ipC, cntC, cb, off4, s_pA + sW * 1024 + dstOff, lane);
        }
        if (++sR == RINGP) sR = 0;
        if (++sW == RINGP) sW = 0;
        // no trailing sync: next (B)-end sync orders pA/pB/kT reuse
    }
}

extern "C" void kernel_launch(void* const* d_in, const int* in_sizes, int n_in,
                              void* d_out, int out_size) {
    const float* inp      = (const float*)d_in[0];
    const float* gating   = (const float*)d_in[1];
    const float* w_in     = (const float*)d_in[2];
    const float* b_in     = (const float*)d_in[3];
    const float* w_rnn    = (const float*)d_in[4];
    const float* b_rnn    = (const float*)d_in[5];
    const float* tau_m    = (const float*)d_in[6];
    const float* tau_n    = (const float*)d_in[7];
    const float* w_ro     = (const float*)d_in[8];
    const float* b_ro     = (const float*)d_in[9];
    const float* tau_m_ro = (const float*)d_in[10];
    const float* mask     = (const float*)d_in[11];
    float* out = (float*)d_out;

    int smem_rec = SMEM_FLOATS * 4 + 256;   // ~154 KB (readout path needs ~88 KB)
    cudaFuncSetAttribute(k_recurrent,
                         cudaFuncAttributeMaxDynamicSharedMemorySize, smem_rec);

    k_init<<<64, 256>>>();

    k_prep<<<NROWS / 8, 256>>>(w_rnn, mask);

    k_recurrent<<<NCTA_TOTAL, NTH, smem_rec>>>(inp, w_in, b_in, gating,
                                               b_rnn, tau_m, tau_n,
                                               w_ro, b_ro, tau_m_ro, out);
}